// round 13
// baseline (speedup 1.0000x reference)
#include <cuda_runtime.h>
#include <math.h>
#include <stdint.h>

#define BATCH   2
#define SEQ     2048
#define DMODEL  1024
#define NHEADS  16
#define HDIM    64
#define MROWS   (BATCH * SEQ)   /* 4096 */
#define SOFT_SCALE 0.18033688011112042f   /* 0.125 * log2(e) */

/* Scratch (allocation-free rule: __device__ globals). */
static __device__ float g_q[MROWS * DMODEL];
static __device__ float g_k[MROWS * DMODEL];
static __device__ float g_v[MROWS * DMODEL];
static __device__ float g_att[MROWS * DMODEL];
static __device__ float g_xt[MROWS * DMODEL];      /* tf32-rounded x      */
static __device__ float g_wqt[DMODEL * DMODEL];    /* W^T, tf32-rounded   */
static __device__ float g_wkt[DMODEL * DMODEL];
static __device__ float g_wvt[DMODEL * DMODEL];
static __device__ float g_wot[DMODEL * DMODEL];

__device__ __forceinline__ uint32_t f2tf32(float f) {
    uint32_t r;
    asm("cvt.rna.tf32.f32 %0, %1;" : "=r"(r) : "f"(f));
    return r;
}
__device__ __forceinline__ float f2tf32f(float f) {
    return __uint_as_float(f2tf32(f));
}

__device__ __forceinline__ void mma_tf32(float c[4],
    uint32_t a0, uint32_t a1, uint32_t a2, uint32_t a3,
    uint32_t b0, uint32_t b1)
{
    asm volatile(
        "mma.sync.aligned.m16n8k8.row.col.f32.tf32.tf32.f32 "
        "{%0,%1,%2,%3}, {%4,%5,%6,%7}, {%8,%9}, {%0,%1,%2,%3};"
        : "+f"(c[0]), "+f"(c[1]), "+f"(c[2]), "+f"(c[3])
        : "r"(a0), "r"(a1), "r"(a2), "r"(a3), "r"(b0), "r"(b1));
}

__device__ __forceinline__ void ldsm_x4(uint32_t r[4], uint32_t addr) {
    asm volatile("ldmatrix.sync.aligned.m8n8.x4.shared.b16 {%0,%1,%2,%3}, [%4];"
        : "=r"(r[0]), "=r"(r[1]), "=r"(r[2]), "=r"(r[3]) : "r"(addr));
}
__device__ __forceinline__ void ldsm_x2(uint32_t r[2], uint32_t addr) {
    asm volatile("ldmatrix.sync.aligned.m8n8.x2.shared.b16 {%0,%1}, [%2];"
        : "=r"(r[0]), "=r"(r[1]) : "r"(addr));
}

__device__ __forceinline__ void cp16(uint32_t dst_smem, const void* src) {
    asm volatile("cp.async.cg.shared.global [%0], [%1], 16;"
                 :: "r"(dst_smem), "l"(src));
}
__device__ __forceinline__ void cp_commit() { asm volatile("cp.async.commit_group;"); }
__device__ __forceinline__ void cp_wait0()  { asm volatile("cp.async.wait_group 0;"); }
__device__ __forceinline__ uint32_t smem_u32(const void* p) {
    return (uint32_t)__cvta_generic_to_shared(p);
}

/* ================================================================== */
/* Prep 1: round x to tf32 values                                      */
/* ================================================================== */
__global__ __launch_bounds__(256) void round_x_kernel(const float* __restrict__ x)
{
    const int idx = blockIdx.x * 256 + threadIdx.x;
    float4 v = ((const float4*)x)[idx];
    v.x = f2tf32f(v.x); v.y = f2tf32f(v.y);
    v.z = f2tf32f(v.z); v.w = f2tf32f(v.w);
    ((float4*)g_xt)[idx] = v;
}

/* ================================================================== */
/* Prep 2: transpose W [k][n] -> Wt [n][k], tf32-rounded               */
/* grid (32, 32, 4), block (32, 8)                                     */
/* ================================================================== */
__global__ __launch_bounds__(256) void wtrans_kernel(
    const float* __restrict__ Wq, const float* __restrict__ Wk,
    const float* __restrict__ Wv, const float* __restrict__ Wo)
{
    __shared__ float tile[32][33];
    const float* W;
    float* Wt;
    if (blockIdx.z == 0)      { W = Wq; Wt = g_wqt; }
    else if (blockIdx.z == 1) { W = Wk; Wt = g_wkt; }
    else if (blockIdx.z == 2) { W = Wv; Wt = g_wvt; }
    else                      { W = Wo; Wt = g_wot; }

    const int tx = threadIdx.x, ty = threadIdx.y;
    const int bx = blockIdx.x, by = blockIdx.y;
#pragma unroll
    for (int j = 0; j < 4; j++) {
        int r = by * 32 + ty + j * 8;
        tile[ty + j * 8][tx] = W[(size_t)r * DMODEL + bx * 32 + tx];
    }
    __syncthreads();
#pragma unroll
    for (int j = 0; j < 4; j++) {
        int n = bx * 32 + ty + j * 8;
        int k = by * 32 + tx;
        Wt[(size_t)n * DMODEL + k] = f2tf32f(tile[tx][ty + j * 8]);
    }
}

/* ================================================================== */
/* TF32 GEMM v5: both operands k-major in smem, fragments via          */
/* ldmatrix (tf32-as-b16-pairs). CTA 128x256, 256 thr, warp 64x64,     */
/* 2-stage cp.async (R8-proven). Inputs must be tf32-valued.           */
/* Row stride 20 floats (80B): ldmatrix rows hit 16B-chunks 5r mod 8   */
/* = all distinct -> conflict-free.                                    */
/* ================================================================== */
#define GM 128
#define GN 256
#define GK 16
#define RSTR 20
#define A_FLOATS (2 * GM * RSTR)            /* 5120  */
#define B_FLOATS (2 * GN * RSTR)            /* 10240 */
#define DSMB ((A_FLOATS + B_FLOATS) * 4)    /* 61440 bytes */

template<bool ROUND_OUT>
__device__ __forceinline__ void gemm_body(
    const float* __restrict__ A, const float* __restrict__ Bt,
    const float* __restrict__ bias, float* __restrict__ C,
    int bx, int by)
{
    extern __shared__ float dsm[];
    float* As = dsm;                 /* [2][GM][RSTR] */
    float* Bs = dsm + A_FLOATS;      /* [2][GN][RSTR] */

    const int tid  = threadIdx.x;
    const int warp = tid >> 5;
    const int lane = tid & 31;
    const int g = lane >> 2;
    const int t = lane & 3;

    const int wm = (warp & 1) * 64;
    const int wn = (warp >> 1) * 64;

    const int brow0 = by * GM;
    const int bcol0 = bx * GN;

    /* ldmatrix per-lane address components */
    const int a_r  = lane & 15;            /* row in 16-row block   */
    const int a_ch = (lane >> 4) * 4;      /* col-half: 0 or 4      */
    const int b_r  = lane & 7;             /* row in 8-row block    */
    const int b_ch = ((lane >> 3) & 1) * 4;

    const uint32_t as_base = smem_u32(As);
    const uint32_t bs_base = smem_u32(Bs);

    /* cp.async maps: A 128x16 = 512 chunks (2/thr); B 256x16 = 1024 (4/thr) */
    const int lrow = tid >> 2;             /* 0..63 */
    const int lch  = (tid & 3) * 4;

    float acc[4][8][4];
#pragma unroll
    for (int mt = 0; mt < 4; mt++)
#pragma unroll
        for (int nt = 0; nt < 8; nt++)
#pragma unroll
            for (int i = 0; i < 4; i++) acc[mt][nt][i] = 0.0f;

    const float* Abase  = A  + (size_t)brow0 * DMODEL;
    const float* Btbase = Bt + (size_t)bcol0 * DMODEL;

    /* prologue: tile 0 */
    {
#pragma unroll
        for (int i = 0; i < 2; i++) {
            const int r = lrow + i * 64;
            cp16(as_base + (uint32_t)(r * RSTR + lch) * 4,
                 Abase + (size_t)r * DMODEL + lch);
        }
#pragma unroll
        for (int i = 0; i < 4; i++) {
            const int r = lrow + i * 64;
            cp16(bs_base + (uint32_t)(r * RSTR + lch) * 4,
                 Btbase + (size_t)r * DMODEL + lch);
        }
        cp_commit();
        cp_wait0();
        __syncthreads();
    }

    const int NIT = DMODEL / GK;   /* 64 */
    for (int it = 0; it < NIT; it++) {
        const int buf = it & 1;
        const uint32_t abuf = as_base + (uint32_t)(buf * GM * RSTR) * 4;
        const uint32_t bbuf = bs_base + (uint32_t)(buf * GN * RSTR) * 4;

        if (it + 1 < NIT) {
            const int nb = (it + 1) & 1;
            const int k0 = (it + 1) * GK;
            const uint32_t anb = as_base + (uint32_t)(nb * GM * RSTR) * 4;
            const uint32_t bnb = bs_base + (uint32_t)(nb * GN * RSTR) * 4;
#pragma unroll
            for (int i = 0; i < 2; i++) {
                const int r = lrow + i * 64;
                cp16(anb + (uint32_t)(r * RSTR + lch) * 4,
                     Abase + (size_t)r * DMODEL + k0 + lch);
            }
#pragma unroll
            for (int i = 0; i < 4; i++) {
                const int r = lrow + i * 64;
                cp16(bnb + (uint32_t)(r * RSTR + lch) * 4,
                     Btbase + (size_t)r * DMODEL + k0 + lch);
            }
            cp_commit();
        }

#pragma unroll
        for (int kk = 0; kk < GK; kk += 8) {
            uint32_t af[4][4];
            uint32_t bf[8][2];
#pragma unroll
            for (int mt = 0; mt < 4; mt++) {
                const int row = wm + mt * 16 + a_r;
                ldsm_x4(af[mt], abuf + (uint32_t)(row * RSTR + kk + a_ch) * 4);
            }
#pragma unroll
            for (int nt = 0; nt < 8; nt++) {
                const int row = wn + nt * 8 + b_r;
                ldsm_x2(bf[nt], bbuf + (uint32_t)(row * RSTR + kk + b_ch) * 4);
            }
#pragma unroll
            for (int mt = 0; mt < 4; mt++)
#pragma unroll
                for (int nt = 0; nt < 8; nt++)
                    mma_tf32(acc[mt][nt],
                             af[mt][0], af[mt][1], af[mt][2], af[mt][3],
                             bf[nt][0], bf[nt][1]);
        }

        if (it + 1 < NIT) {
            cp_wait0();
            __syncthreads();
        }
    }

    /* epilogue */
#pragma unroll
    for (int mt = 0; mt < 4; mt++) {
#pragma unroll
        for (int nt = 0; nt < 8; nt++) {
            const int row = brow0 + wm + mt * 16 + g;
            const int col = bcol0 + wn + nt * 8 + t * 2;
            const float b0 = bias[col];
            const float b1 = bias[col + 1];
            float2 r0, r1;
            r0.x = acc[mt][nt][0] + b0;
            r0.y = acc[mt][nt][1] + b1;
            r1.x = acc[mt][nt][2] + b0;
            r1.y = acc[mt][nt][3] + b1;
            if (ROUND_OUT) {
                r0.x = f2tf32f(r0.x); r0.y = f2tf32f(r0.y);
                r1.x = f2tf32f(r1.x); r1.y = f2tf32f(r1.y);
            }
            *(float2*)(C + (size_t)row * DMODEL + col)       = r0;
            *(float2*)(C + (size_t)(row + 8) * DMODEL + col) = r1;
        }
    }
}

__global__ __launch_bounds__(256) void gemm_round_kernel(
    const float* __restrict__ A, const float* __restrict__ Bt,
    const float* __restrict__ bias, float* __restrict__ C)
{
    gemm_body<true>(A, Bt, bias, C, blockIdx.x, blockIdx.y);
}

__global__ __launch_bounds__(256) void gemm_plain_kernel(
    const float* __restrict__ A, const float* __restrict__ Bt,
    const float* __restrict__ bias, float* __restrict__ C)
{
    gemm_body<false>(A, Bt, bias, C, blockIdx.x, blockIdx.y);
}

/* ================================================================== */
/* Tensor-core flash attention (R8, unchanged: tf32 mma, cp.async K/V  */
/* staging, static-max softmax; epilogue writes tf32-rounded att).     */
/* ================================================================== */
#define QT   128
#define KVT  32
#define KSTR 68
#define VSTR 72
#define PSTR 36

__global__ __launch_bounds__(256) void attn_mma_kernel(
    const float* __restrict__ Q, const float* __restrict__ K,
    const float* __restrict__ V, float* __restrict__ O)
{
    __shared__ uint32_t Ks[2][KVT][KSTR];
    __shared__ uint32_t Vs[2][KVT][VSTR];
    __shared__ uint32_t Ps[8][16][PSTR];

    const int tid  = threadIdx.x;
    const int warp = tid >> 5;
    const int lane = tid & 31;
    const int g = lane >> 2;
    const int t = lane & 3;
    const int bh = blockIdx.y;
    const int b  = bh / NHEADS;
    const int h  = bh % NHEADS;
    const int q0 = blockIdx.x * QT + warp * 16;

    const float* qbase = Q + (size_t)(b * SEQ + q0) * DMODEL + h * HDIM;
    uint32_t qa[8][4];
#pragma unroll
    for (int kk = 0; kk < 8; kk++) {
        qa[kk][0] = f2tf32(qbase[(size_t)g       * DMODEL + kk * 8 + t    ] * SOFT_SCALE);
        qa[kk][1] = f2tf32(qbase[(size_t)(g + 8) * DMODEL + kk * 8 + t    ] * SOFT_SCALE);
        qa[kk][2] = f2tf32(qbase[(size_t)g       * DMODEL + kk * 8 + 4 + t] * SOFT_SCALE);
        qa[kk][3] = f2tf32(qbase[(size_t)(g + 8) * DMODEL + kk * 8 + 4 + t] * SOFT_SCALE);
    }

    float of[8][4];
#pragma unroll
    for (int dt = 0; dt < 8; dt++)
#pragma unroll
        for (int i = 0; i < 4; i++) of[dt][i] = 0.0f;
    float l0 = 0.0f, l1 = 0.0f;

    const float* kbase = K + (size_t)b * SEQ * DMODEL + h * HDIM;
    const float* vbase = V + (size_t)b * SEQ * DMODEL + h * HDIM;

    const int key0 = tid >> 4;
    const int key1 = (256 + tid) >> 4;
    const int dg   = (tid & 15) << 2;

    {
        const size_t g0 = (size_t)key0 * DMODEL + dg;
        const size_t g1 = (size_t)key1 * DMODEL + dg;
        cp16(smem_u32(&Ks[0][key0][dg]), kbase + g0);
        cp16(smem_u32(&Ks[0][key1][dg]), kbase + g1);
        cp16(smem_u32(&Vs[0][key0][dg]), vbase + g0);
        cp16(smem_u32(&Vs[0][key1][dg]), vbase + g1);
        cp_commit();
        cp_wait0();
        __syncthreads();
    }

    const int NTILE = SEQ / KVT;   /* 64 */
    for (int it = 0; it < NTILE; it++) {
        const int buf = it & 1;

        if (it + 1 < NTILE) {
            const int nb = buf ^ 1;
            const size_t base = (size_t)(it + 1) * KVT * DMODEL;
            const size_t g0 = base + (size_t)key0 * DMODEL + dg;
            const size_t g1 = base + (size_t)key1 * DMODEL + dg;
            cp16(smem_u32(&Ks[nb][key0][dg]), kbase + g0);
            cp16(smem_u32(&Ks[nb][key1][dg]), kbase + g1);
            cp16(smem_u32(&Vs[nb][key0][dg]), vbase + g0);
            cp16(smem_u32(&Vs[nb][key1][dg]), vbase + g1);
            cp_commit();
        }

        float sc[4][4];
#pragma unroll
        for (int nt = 0; nt < 4; nt++)
#pragma unroll
            for (int i = 0; i < 4; i++) sc[nt][i] = 0.0f;
#pragma unroll
        for (int kk = 0; kk < 8; kk++) {
#pragma unroll
            for (int nt = 0; nt < 4; nt++) {
                const uint32_t b0 = Ks[buf][nt * 8 + g][kk * 8 + t];
                const uint32_t b1 = Ks[buf][nt * 8 + g][kk * 8 + 4 + t];
                mma_tf32(sc[nt], qa[kk][0], qa[kk][1], qa[kk][2], qa[kk][3], b0, b1);
            }
        }

        __syncwarp();

#pragma unroll
        for (int nt = 0; nt < 4; nt++) {
            const float p0 = exp2f(sc[nt][0]);
            const float p1 = exp2f(sc[nt][1]);
            const float p2 = exp2f(sc[nt][2]);
            const float p3 = exp2f(sc[nt][3]);
            l0 += p0 + p1;
            l1 += p2 + p3;
            uint2 lo, hi;
            lo.x = f2tf32(p0); lo.y = f2tf32(p1);
            hi.x = f2tf32(p2); hi.y = f2tf32(p3);
            *(uint2*)&Ps[warp][g    ][nt * 8 + 2 * t] = lo;
            *(uint2*)&Ps[warp][g + 8][nt * 8 + 2 * t] = hi;
        }
        __syncwarp();

#pragma unroll
        for (int kk = 0; kk < 4; kk++) {
            const uint32_t pa0 = Ps[warp][g    ][kk * 8 + t];
            const uint32_t pa1 = Ps[warp][g + 8][kk * 8 + t];
            const uint32_t pa2 = Ps[warp][g    ][kk * 8 + 4 + t];
            const uint32_t pa3 = Ps[warp][g + 8][kk * 8 + 4 + t];
#pragma unroll
            for (int dt = 0; dt < 8; dt++) {
                const uint32_t b0 = Vs[buf][kk * 8 + t    ][dt * 8 + g];
                const uint32_t b1 = Vs[buf][kk * 8 + 4 + t][dt * 8 + g];
                mma_tf32(of[dt], pa0, pa1, pa2, pa3, b0, b1);
            }
        }

        if (it + 1 < NTILE) {
            cp_wait0();
            __syncthreads();
        }
    }

    l0 += __shfl_xor_sync(0xffffffffu, l0, 1);
    l0 += __shfl_xor_sync(0xffffffffu, l0, 2);
    l1 += __shfl_xor_sync(0xffffffffu, l1, 1);
    l1 += __shfl_xor_sync(0xffffffffu, l1, 2);

    const float inv0 = 1.0f / l0;
    const float inv1 = 1.0f / l1;
    float* ob = O + (size_t)(b * SEQ + q0) * DMODEL + h * HDIM;
#pragma unroll
    for (int dt = 0; dt < 8; dt++) {
        float2 r0, r1;
        r0.x = f2tf32f(of[dt][0] * inv0); r0.y = f2tf32f(of[dt][1] * inv0);
        r1.x = f2tf32f(of[dt][2] * inv1); r1.y = f2tf32f(of[dt][3] * inv1);
        *(float2*)(ob + (size_t)g       * DMODEL + dt * 8 + 2 * t) = r0;
        *(float2*)(ob + (size_t)(g + 8) * DMODEL + dt * 8 + 2 * t) = r1;
    }
}

/* ------------------------------------------------------------------ */
extern "C" void kernel_launch(void* const* d_in, const int* in_sizes, int n_in,
                              void* d_out, int out_size)
{
    const float* x  = (const float*)d_in[0];
    const float* Wq = (const float*)d_in[1];
    const float* bq = (const float*)d_in[2];
    const float* Wk = (const float*)d_in[3];
    const float* bk = (const float*)d_in[4];
    const float* Wv = (const float*)d_in[5];
    const float* bv = (const float*)d_in[6];
    const float* Wo = (const float*)d_in[7];
    const float* bo = (const float*)d_in[8];
    float* out = (float*)d_out;

    float *q, *k, *v, *att, *xt, *wqt, *wkt, *wvt, *wot;
    cudaGetSymbolAddress((void**)&q,   g_q);
    cudaGetSymbolAddress((void**)&k,   g_k);
    cudaGetSymbolAddress((void**)&v,   g_v);
    cudaGetSymbolAddress((void**)&att, g_att);
    cudaGetSymbolAddress((void**)&xt,  g_xt);
    cudaGetSymbolAddress((void**)&wqt, g_wqt);
    cudaGetSymbolAddress((void**)&wkt, g_wkt);
    cudaGetSymbolAddress((void**)&wvt, g_wvt);
    cudaGetSymbolAddress((void**)&wot, g_wot);

    cudaFuncSetAttribute(gemm_round_kernel,
        cudaFuncAttributeMaxDynamicSharedMemorySize, DSMB);
    cudaFuncSetAttribute(gemm_plain_kernel,
        cudaFuncAttributeMaxDynamicSharedMemorySize, DSMB);

    /* prep */
    round_x_kernel<<<MROWS * DMODEL / 4 / 256, 256>>>(x);
    wtrans_kernel<<<dim3(32, 32, 4), dim3(32, 8)>>>(Wq, Wk, Wv, Wo);

    /* projections */
    dim3 gproj(DMODEL / GN, MROWS / GM);   /* (4, 32) = 128 CTAs */
    gemm_round_kernel<<<gproj, 256, DSMB>>>(xt, wqt, bq, q);
    gemm_round_kernel<<<gproj, 256, DSMB>>>(xt, wkt, bk, k);
    gemm_round_kernel<<<gproj, 256, DSMB>>>(xt, wvt, bv, v);

    /* attention */
    dim3 gattn(SEQ / QT, BATCH * NHEADS);  /* (16, 32) */
    attn_mma_kernel<<<gattn, 256>>>(q, k, v, att);

    /* output projection */
    gemm_plain_kernel<<<gproj, 256, DSMB>>>(att, wot, bo, out);
}

// round 14
// speedup vs baseline: 1.0851x; 1.0851x over previous
#include <cuda_runtime.h>
#include <math.h>
#include <stdint.h>

#define BATCH   2
#define SEQ     2048
#define DMODEL  1024
#define NHEADS  16
#define HDIM    64
#define MROWS   (BATCH * SEQ)   /* 4096 */
#define SOFT_SCALE 0.18033688011112042f   /* 0.125 * log2(e) */

/* Scratch (allocation-free rule: __device__ globals). */
static __device__ float g_q[MROWS * DMODEL];
static __device__ float g_k[MROWS * DMODEL];
static __device__ float g_v[MROWS * DMODEL];
static __device__ float g_att[MROWS * DMODEL];
static __device__ float g_xt[MROWS * DMODEL];           /* tf32-rounded x  */
static __device__ float g_wq[DMODEL * DMODEL];
static __device__ float g_wk[DMODEL * DMODEL];
static __device__ float g_wv[DMODEL * DMODEL];
static __device__ float g_wo[DMODEL * DMODEL];

__device__ __forceinline__ uint32_t f2tf32(float f) {
    uint32_t r;
    asm("cvt.rna.tf32.f32 %0, %1;" : "=r"(r) : "f"(f));
    return r;
}
__device__ __forceinline__ float f2tf32f(float f) {
    return __uint_as_float(f2tf32(f));
}

__device__ __forceinline__ void mma_tf32(float c[4],
    uint32_t a0, uint32_t a1, uint32_t a2, uint32_t a3,
    uint32_t b0, uint32_t b1)
{
    asm volatile(
        "mma.sync.aligned.m16n8k8.row.col.f32.tf32.tf32.f32 "
        "{%0,%1,%2,%3}, {%4,%5,%6,%7}, {%8,%9}, {%0,%1,%2,%3};"
        : "+f"(c[0]), "+f"(c[1]), "+f"(c[2]), "+f"(c[3])
        : "r"(a0), "r"(a1), "r"(a2), "r"(a3), "r"(b0), "r"(b1));
}

__device__ __forceinline__ void cp16(uint32_t dst_smem, const void* src) {
    asm volatile("cp.async.cg.shared.global [%0], [%1], 16;"
                 :: "r"(dst_smem), "l"(src));
}
__device__ __forceinline__ void cp_commit() { asm volatile("cp.async.commit_group;"); }
__device__ __forceinline__ void cp_wait0()  { asm volatile("cp.async.wait_group 0;"); }
__device__ __forceinline__ uint32_t smem_u32(const void* p) {
    return (uint32_t)__cvta_generic_to_shared(p);
}

/* ================================================================== */
/* Prep: round x and all W to tf32 values (exact mma inputs later).   */
/* ================================================================== */
__global__ __launch_bounds__(256) void round_prep_kernel(
    const float* __restrict__ x,
    const float* __restrict__ Wq, const float* __restrict__ Wk,
    const float* __restrict__ Wv, const float* __restrict__ Wo)
{
    const int seg = blockIdx.y;
    const float* src;
    float* dst;
    const int M1 = DMODEL * DMODEL;   /* 1M floats */
    if (seg < 4)      { src = x  + (size_t)seg * M1; dst = g_xt + (size_t)seg * M1; }
    else if (seg == 4){ src = Wq; dst = g_wq; }
    else if (seg == 5){ src = Wk; dst = g_wk; }
    else if (seg == 6){ src = Wv; dst = g_wv; }
    else              { src = Wo; dst = g_wo; }

    const int idx = blockIdx.x * blockDim.x + threadIdx.x;
    float4 v = ((const float4*)src)[idx];
    v.x = f2tf32f(v.x); v.y = f2tf32f(v.y);
    v.z = f2tf32f(v.z); v.w = f2tf32f(v.w);
    ((float4*)dst)[idx] = v;
}

/* ================================================================== */
/* TF32 GEMM (R8 exact, 66.2us proven): cp.async double-buffered,     */
/* CTA 128x256, 256 thr, warp 64x64. Inputs must be tf32-valued.      */
/* ASTR=20 / BSTR=264: conflict-free frag loads; 16B-aligned dsts.    */
/* ================================================================== */
#define GM 128
#define GN 256
#define GK 16
#define ASTR 20
#define BSTR 264

template<bool ROUND_OUT>
__device__ __forceinline__ void gemm_body_ca(
    const float* __restrict__ A, const float* __restrict__ W,
    const float* __restrict__ bias, float* __restrict__ C,
    int M, int N, int K, int bx, int by)
{
    __shared__ float As[2][GM][ASTR];
    __shared__ float Bs[2][GK][BSTR];

    const int tid  = threadIdx.x;
    const int warp = tid >> 5;
    const int lane = tid & 31;
    const int g = lane >> 2;
    const int t = lane & 3;

    const int wm = (warp & 1) * 64;
    const int wn = (warp >> 1) * 64;

    const int brow0 = by * GM;
    const int bcol0 = bx * GN;

    const int arow0 = tid >> 2;          /* 0..63  */
    const int ka    = (tid & 3) * 4;     /* 0,4,8,12 */
    const int browb = tid >> 6;          /* 0..3 */
    const int colb  = (tid & 63) * 4;    /* 0..252 */

    float acc[4][8][4];
#pragma unroll
    for (int mt = 0; mt < 4; mt++)
#pragma unroll
        for (int nt = 0; nt < 8; nt++)
#pragma unroll
            for (int i = 0; i < 4; i++) acc[mt][nt][i] = 0.0f;

    const float* Abase = A + (size_t)brow0 * K;
    const float* Wbase = W + bcol0;

    {
        cp16(smem_u32(&As[0][arow0     ][ka]), Abase + (size_t)(arow0     ) * K + ka);
        cp16(smem_u32(&As[0][arow0 + 64][ka]), Abase + (size_t)(arow0 + 64) * K + ka);
#pragma unroll
        for (int j = 0; j < 4; j++)
            cp16(smem_u32(&Bs[0][browb + 4 * j][colb]),
                 Wbase + (size_t)(browb + 4 * j) * N + colb);
        cp_commit();
        cp_wait0();
        __syncthreads();
    }

    const int NIT = K / GK;
    for (int it = 0; it < NIT; it++) {
        const int buf = it & 1;

        if (it + 1 < NIT) {
            const int nb = buf ^ 1;
            const int k0 = (it + 1) * GK;
            cp16(smem_u32(&As[nb][arow0     ][ka]), Abase + (size_t)(arow0     ) * K + k0 + ka);
            cp16(smem_u32(&As[nb][arow0 + 64][ka]), Abase + (size_t)(arow0 + 64) * K + k0 + ka);
#pragma unroll
            for (int j = 0; j < 4; j++)
                cp16(smem_u32(&Bs[nb][browb + 4 * j][colb]),
                     Wbase + (size_t)(k0 + browb + 4 * j) * N + colb);
            cp_commit();
        }

#pragma unroll
        for (int kk = 0; kk < GK; kk += 8) {
            uint32_t af[4][4];
            uint32_t bf[8][2];
#pragma unroll
            for (int mt = 0; mt < 4; mt++) {
                const int m0 = wm + mt * 16;
                af[mt][0] = __float_as_uint(As[buf][m0 + g    ][kk + t    ]);
                af[mt][1] = __float_as_uint(As[buf][m0 + 8 + g][kk + t    ]);
                af[mt][2] = __float_as_uint(As[buf][m0 + g    ][kk + 4 + t]);
                af[mt][3] = __float_as_uint(As[buf][m0 + 8 + g][kk + 4 + t]);
            }
#pragma unroll
            for (int nt = 0; nt < 8; nt++) {
                const int n0 = wn + nt * 8;
                bf[nt][0] = __float_as_uint(Bs[buf][kk + t    ][n0 + g]);
                bf[nt][1] = __float_as_uint(Bs[buf][kk + 4 + t][n0 + g]);
            }
#pragma unroll
            for (int mt = 0; mt < 4; mt++)
#pragma unroll
                for (int nt = 0; nt < 8; nt++)
                    mma_tf32(acc[mt][nt],
                             af[mt][0], af[mt][1], af[mt][2], af[mt][3],
                             bf[nt][0], bf[nt][1]);
        }

        if (it + 1 < NIT) {
            cp_wait0();
            __syncthreads();
        }
    }

#pragma unroll
    for (int mt = 0; mt < 4; mt++) {
#pragma unroll
        for (int nt = 0; nt < 8; nt++) {
            const int row = brow0 + wm + mt * 16 + g;
            const int col = bcol0 + wn + nt * 8 + t * 2;
            const float b0 = bias[col];
            const float b1 = bias[col + 1];
            float2 r0, r1;
            r0.x = acc[mt][nt][0] + b0;
            r0.y = acc[mt][nt][1] + b1;
            r1.x = acc[mt][nt][2] + b0;
            r1.y = acc[mt][nt][3] + b1;
            if (ROUND_OUT) {
                r0.x = f2tf32f(r0.x); r0.y = f2tf32f(r0.y);
                r1.x = f2tf32f(r1.x); r1.y = f2tf32f(r1.y);
            }
            *(float2*)(C + (size_t)row * N + col)       = r0;
            *(float2*)(C + (size_t)(row + 8) * N + col) = r1;
        }
    }
}

/* fused QKV via blockIdx.z */
__global__ __launch_bounds__(256) void gemm_qkv_kernel(const float* __restrict__ xt_dummy,
    const float* __restrict__ bq, const float* __restrict__ bk,
    const float* __restrict__ bv)
{
    const float* W; const float* bias; float* C;
    if (blockIdx.z == 0)      { W = g_wq; bias = bq; C = g_q; }
    else if (blockIdx.z == 1) { W = g_wk; bias = bk; C = g_k; }
    else                      { W = g_wv; bias = bv; C = g_v; }
    gemm_body_ca<true>(g_xt, W, bias, C, MROWS, DMODEL, DMODEL,
                       blockIdx.x, blockIdx.y);
}

__global__ __launch_bounds__(256) void gemm_ca_plain_kernel(
    const float* __restrict__ A, const float* __restrict__ W,
    const float* __restrict__ bias, float* __restrict__ C,
    int M, int N, int K)
{
    gemm_body_ca<false>(A, W, bias, C, M, N, K, blockIdx.x, blockIdx.y);
}

/* ================================================================== */
/* Tensor-core flash attention v4: R8 math, but 64-key staged tiles   */
/* (two 32-key compute halves) -> half the cp.async waits & barriers. */
/* Dynamic smem (88 KB): Ks[2][64][68] | Vs[2][64][72] | Ps[8][16][36]*/
/* ================================================================== */
#define QT   128
#define KVT  64
#define KHALF 32
#define KSTR 68
#define VSTR 72
#define PSTR 36
#define KS_U32 (2 * KVT * KSTR)            /* 8704  u32 */
#define VS_U32 (2 * KVT * VSTR)            /* 9216  u32 */
#define PS_U32 (8 * 16 * PSTR)             /* 4608  u32 */
#define ATT_DSMB ((KS_U32 + VS_U32 + PS_U32) * 4)   /* 90112 B */

__global__ __launch_bounds__(256) void attn_mma_kernel(
    const float* __restrict__ Q, const float* __restrict__ K,
    const float* __restrict__ V, float* __restrict__ O)
{
    extern __shared__ uint32_t dsm_att[];
    uint32_t* sKs = dsm_att;                      /* [buf][key][KSTR] */
    uint32_t* sVs = dsm_att + KS_U32;             /* [buf][key][VSTR] */
    uint32_t* sPs = dsm_att + KS_U32 + VS_U32;    /* [warp][row][PSTR] */

    const int tid  = threadIdx.x;
    const int warp = tid >> 5;
    const int lane = tid & 31;
    const int g = lane >> 2;
    const int t = lane & 3;
    const int bh = blockIdx.y;
    const int b  = bh / NHEADS;
    const int h  = bh % NHEADS;
    const int q0 = blockIdx.x * QT + warp * 16;

    const float* qbase = Q + (size_t)(b * SEQ + q0) * DMODEL + h * HDIM;
    uint32_t qa[8][4];
#pragma unroll
    for (int kk = 0; kk < 8; kk++) {
        qa[kk][0] = f2tf32(qbase[(size_t)g       * DMODEL + kk * 8 + t    ] * SOFT_SCALE);
        qa[kk][1] = f2tf32(qbase[(size_t)(g + 8) * DMODEL + kk * 8 + t    ] * SOFT_SCALE);
        qa[kk][2] = f2tf32(qbase[(size_t)g       * DMODEL + kk * 8 + 4 + t] * SOFT_SCALE);
        qa[kk][3] = f2tf32(qbase[(size_t)(g + 8) * DMODEL + kk * 8 + 4 + t] * SOFT_SCALE);
    }

    float of[8][4];
#pragma unroll
    for (int dt = 0; dt < 8; dt++)
#pragma unroll
        for (int i = 0; i < 4; i++) of[dt][i] = 0.0f;
    float l0 = 0.0f, l1 = 0.0f;

    const float* kbase = K + (size_t)b * SEQ * DMODEL + h * HDIM;
    const float* vbase = V + (size_t)b * SEQ * DMODEL + h * HDIM;

    /* loaders: 64 keys x 16 chunks = 1024 chunks/tensor, 4/thread */
    const int dg = (tid & 15) << 2;

    /* prologue: tile 0 */
    {
#pragma unroll
        for (int i = 0; i < 4; i++) {
            const int key = (tid + i * 256) >> 4;
            const size_t go = (size_t)key * DMODEL + dg;
            cp16(smem_u32(&sKs[(size_t)key * KSTR + dg]), kbase + go);
            cp16(smem_u32(&sVs[(size_t)key * VSTR + dg]), vbase + go);
        }
        cp_commit();
        cp_wait0();
        __syncthreads();
    }

    const int NTILE = SEQ / KVT;   /* 32 */
    for (int it = 0; it < NTILE; it++) {
        const int buf = it & 1;
        uint32_t* Kb = sKs + buf * KVT * KSTR;
        uint32_t* Vb = sVs + buf * KVT * VSTR;

        if (it + 1 < NTILE) {
            const int nb = buf ^ 1;
            uint32_t* Kn = sKs + nb * KVT * KSTR;
            uint32_t* Vn = sVs + nb * KVT * VSTR;
            const size_t base = (size_t)(it + 1) * KVT * DMODEL;
#pragma unroll
            for (int i = 0; i < 4; i++) {
                const int key = (tid + i * 256) >> 4;
                const size_t go = base + (size_t)key * DMODEL + dg;
                cp16(smem_u32(&Kn[(size_t)key * KSTR + dg]), kbase + go);
                cp16(smem_u32(&Vn[(size_t)key * VSTR + dg]), vbase + go);
            }
            cp_commit();
        }

        /* two 32-key halves, identical math to R8 */
#pragma unroll
        for (int hf = 0; hf < 2; hf++) {
            const uint32_t* Kh = Kb + hf * KHALF * KSTR;
            const uint32_t* Vh = Vb + hf * KHALF * VSTR;

            float sc[4][4];
#pragma unroll
            for (int nt = 0; nt < 4; nt++)
#pragma unroll
                for (int i = 0; i < 4; i++) sc[nt][i] = 0.0f;
#pragma unroll
            for (int kk = 0; kk < 8; kk++) {
#pragma unroll
                for (int nt = 0; nt < 4; nt++) {
                    const uint32_t b0 = Kh[(nt * 8 + g) * KSTR + kk * 8 + t];
                    const uint32_t b1 = Kh[(nt * 8 + g) * KSTR + kk * 8 + 4 + t];
                    mma_tf32(sc[nt], qa[kk][0], qa[kk][1], qa[kk][2], qa[kk][3], b0, b1);
                }
            }

            __syncwarp();   /* previous PV reads of Ps done before overwrite */

#pragma unroll
            for (int nt = 0; nt < 4; nt++) {
                const float p0 = exp2f(sc[nt][0]);
                const float p1 = exp2f(sc[nt][1]);
                const float p2 = exp2f(sc[nt][2]);
                const float p3 = exp2f(sc[nt][3]);
                l0 += p0 + p1;
                l1 += p2 + p3;
                uint2 lo, hi;
                lo.x = f2tf32(p0); lo.y = f2tf32(p1);
                hi.x = f2tf32(p2); hi.y = f2tf32(p3);
                *(uint2*)&sPs[(warp * 16 + g    ) * PSTR + nt * 8 + 2 * t] = lo;
                *(uint2*)&sPs[(warp * 16 + g + 8) * PSTR + nt * 8 + 2 * t] = hi;
            }
            __syncwarp();

#pragma unroll
            for (int kk = 0; kk < 4; kk++) {
                const uint32_t pa0 = sPs[(warp * 16 + g    ) * PSTR + kk * 8 + t];
                const uint32_t pa1 = sPs[(warp * 16 + g + 8) * PSTR + kk * 8 + t];
                const uint32_t pa2 = sPs[(warp * 16 + g    ) * PSTR + kk * 8 + 4 + t];
                const uint32_t pa3 = sPs[(warp * 16 + g + 8) * PSTR + kk * 8 + 4 + t];
#pragma unroll
                for (int dt = 0; dt < 8; dt++) {
                    const uint32_t b0 = Vh[(kk * 8 + t    ) * VSTR + dt * 8 + g];
                    const uint32_t b1 = Vh[(kk * 8 + 4 + t) * VSTR + dt * 8 + g];
                    mma_tf32(of[dt], pa0, pa1, pa2, pa3, b0, b1);
                }
            }
        }

        if (it + 1 < NTILE) {
            cp_wait0();
            __syncthreads();
        }
    }

    l0 += __shfl_xor_sync(0xffffffffu, l0, 1);
    l0 += __shfl_xor_sync(0xffffffffu, l0, 2);
    l1 += __shfl_xor_sync(0xffffffffu, l1, 1);
    l1 += __shfl_xor_sync(0xffffffffu, l1, 2);

    const float inv0 = 1.0f / l0;
    const float inv1 = 1.0f / l1;
    float* ob = O + (size_t)(b * SEQ + q0) * DMODEL + h * HDIM;
#pragma unroll
    for (int dt = 0; dt < 8; dt++) {
        float2 r0, r1;
        /* round: att feeds the Wo GEMM, which needs exact tf32 inputs */
        r0.x = f2tf32f(of[dt][0] * inv0); r0.y = f2tf32f(of[dt][1] * inv0);
        r1.x = f2tf32f(of[dt][2] * inv1); r1.y = f2tf32f(of[dt][3] * inv1);
        *(float2*)(ob + (size_t)g       * DMODEL + dt * 8 + 2 * t) = r0;
        *(float2*)(ob + (size_t)(g + 8) * DMODEL + dt * 8 + 2 * t) = r1;
    }
}

/* ------------------------------------------------------------------ */
extern "C" void kernel_launch(void* const* d_in, const int* in_sizes, int n_in,
                              void* d_out, int out_size)
{
    const float* x  = (const float*)d_in[0];
    const float* Wq = (const float*)d_in[1];
    const float* bq = (const float*)d_in[2];
    const float* Wk = (const float*)d_in[3];
    const float* bk = (const float*)d_in[4];
    const float* Wv = (const float*)d_in[5];
    const float* bv = (const float*)d_in[6];
    const float* Wo = (const float*)d_in[7];
    const float* bo = (const float*)d_in[8];
    float* out = (float*)d_out;

    float *q, *k, *v, *att, *xt, *wo;
    cudaGetSymbolAddress((void**)&q,   g_q);
    cudaGetSymbolAddress((void**)&k,   g_k);
    cudaGetSymbolAddress((void**)&v,   g_v);
    cudaGetSymbolAddress((void**)&att, g_att);
    cudaGetSymbolAddress((void**)&xt,  g_xt);
    cudaGetSymbolAddress((void**)&wo,  g_wo);

    cudaFuncSetAttribute(attn_mma_kernel,
        cudaFuncAttributeMaxDynamicSharedMemorySize, ATT_DSMB);

    /* prep: round x + all W to tf32 values */
    dim3 gprep(DMODEL * DMODEL / 4 / 256, 8);   /* (1024, 8) */
    round_prep_kernel<<<gprep, 256>>>(x, Wq, Wk, Wv, Wo);

    /* fused QKV: (4, 32, 3) = 384 CTAs */
    dim3 gqkv(DMODEL / GN, MROWS / GM, 3);
    gemm_qkv_kernel<<<gqkv, 256>>>(xt, bq, bk, bv);

    dim3 gattn(SEQ / QT, BATCH * NHEADS);  /* (16, 32) */
    attn_mma_kernel<<<gattn, 256, ATT_DSMB>>>(q, k, v, att);

    dim3 gproj(DMODEL / GN, MROWS / GM);   /* (4, 32) = 128 CTAs */
    gemm_ca_plain_kernel<<<gproj, 256>>>(att, wo, bo, out, MROWS, DMODEL, DMODEL);
}